// round 1
// baseline (speedup 1.0000x reference)
#include <cuda_runtime.h>
#include <math.h>

#define Bsz  2
#define Nseq 2048
#define Emb  1024
#define Hh   16
#define Dd   64
#define Mrows (Bsz * Nseq)      // 4096
#define E3   (3 * Emb)          // 3072

// Scratch (device globals: allocation-free per harness rules)
__device__ float g_q[Bsz * Hh * Nseq * Dd];   // [B,H,N,D]
__device__ float g_k[Bsz * Hh * Nseq * Dd];
__device__ float g_v[Bsz * Hh * Nseq * Dd];
__device__ float g_ao[Mrows * Emb];           // attention out, [B*N, E] (h*D+d contiguous)

// ---------------------------------------------------------------------------
// QKV GEMM: [4096,1024] @ [1024,3072] + bias, scattered into Q/K/V [B,H,N,D]
// Tile: BM=64, BN=64, BK=16; 256 threads; 4x4 microtile per thread.
// ---------------------------------------------------------------------------
__global__ __launch_bounds__(256) void qkv_gemm_kernel(
    const float* __restrict__ X, const float* __restrict__ Wq,
    const float* __restrict__ bias)
{
    __shared__ float As[16][65];   // A^T tile: As[k][m]
    __shared__ float Bs[16][65];   // B tile:  Bs[k][n]

    const int tid = threadIdx.x;
    const int tx = tid & 15;       // 0..15 -> n
    const int ty = tid >> 4;       // 0..15 -> m
    const int m0 = blockIdx.y * 64;
    const int n0 = blockIdx.x * 64;

    float acc[4][4] = {};

    for (int k0 = 0; k0 < Emb; k0 += 16) {
        #pragma unroll
        for (int i = 0; i < 4; i++) {
            int e = tid + i * 256;             // 0..1023, r=e>>4 (64), c=e&15
            As[e & 15][e >> 4] = X[(m0 + (e >> 4)) * Emb + k0 + (e & 15)];
        }
        #pragma unroll
        for (int i = 0; i < 4; i++) {
            int e = tid + i * 256;             // r=e>>6 (16), c=e&63
            Bs[e >> 6][e & 63] = Wq[(k0 + (e >> 6)) * E3 + n0 + (e & 63)];
        }
        __syncthreads();
        #pragma unroll
        for (int kk = 0; kk < 16; kk++) {
            float a[4], b[4];
            #pragma unroll
            for (int i = 0; i < 4; i++) a[i] = As[kk][ty * 4 + i];
            #pragma unroll
            for (int j = 0; j < 4; j++) b[j] = Bs[kk][tx * 4 + j];
            #pragma unroll
            for (int i = 0; i < 4; i++)
                #pragma unroll
                for (int j = 0; j < 4; j++)
                    acc[i][j] += a[i] * b[j];
        }
        __syncthreads();
    }

    // Epilogue: +bias, scatter to q/k/v in [B,H,N,D]
    #pragma unroll
    for (int i = 0; i < 4; i++) {
        int m = m0 + ty * 4 + i;
        int bb = m >> 11;                 // / Nseq
        int tok = m & (Nseq - 1);
        #pragma unroll
        for (int j = 0; j < 4; j++) {
            int n = n0 + tx * 4 + j;
            float v = acc[i][j] + bias[n];
            int part = n >> 10;           // 0=q,1=k,2=v
            int h = (n >> 6) & (Hh - 1);
            int d = n & (Dd - 1);
            float* dst = (part == 0) ? g_q : ((part == 1) ? g_k : g_v);
            dst[(((bb * Hh + h) * Nseq) + tok) * Dd + d] = v;
        }
    }
}

// ---------------------------------------------------------------------------
// Flash attention, fp32. One block = one (b,h) x 64-query tile.
// 256 threads, 4x4 microtiles for both S=QK^T and O+=P@V.
// ---------------------------------------------------------------------------
__global__ __launch_bounds__(256) void attn_kernel()
{
    extern __shared__ float sm[];
    const int SW = 65;                    // padded row stride
    float* Qs = sm;                       // [64][65]
    float* Ks = sm + 64 * SW;             // [64][65]
    float* Vs = sm + 2 * 64 * SW;         // [64][65]
    float* Ps = sm + 3 * 64 * SW;         // [64][65]

    const int tid = threadIdx.x;
    const int tx = tid & 15;
    const int ty = tid >> 4;
    const int bh = blockIdx.y;            // 0..31  (b*16+h)
    const int q0 = blockIdx.x * 64;

    const float* Qg = g_q + (bh * Nseq + q0) * Dd;
    const float* Kg = g_k + (size_t)bh * Nseq * Dd;
    const float* Vg = g_v + (size_t)bh * Nseq * Dd;

    // load Q tile [64][64]
    #pragma unroll
    for (int i = 0; i < 16; i++) {
        int e = tid + i * 256;            // r=e>>6, c=e&63 ; Qg is contiguous 64-wide
        Qs[(e >> 6) * SW + (e & 63)] = Qg[e];
    }

    float m_i[4], l_i[4], o[4][4];
    #pragma unroll
    for (int i = 0; i < 4; i++) {
        m_i[i] = -INFINITY;
        l_i[i] = 0.0f;
        #pragma unroll
        for (int j = 0; j < 4; j++) o[i][j] = 0.0f;
    }
    __syncthreads();

    for (int t = 0; t < Nseq / 64; t++) {
        const float* Kt = Kg + t * 64 * Dd;
        const float* Vt = Vg + t * 64 * Dd;
        #pragma unroll
        for (int i = 0; i < 16; i++) {
            int e = tid + i * 256;
            int r = e >> 6, c = e & 63;
            Ks[r * SW + c] = Kt[e];
            Vs[r * SW + c] = Vt[e];
        }
        __syncthreads();

        // S = Q K^T (this thread: rows 4ty..4ty+3, keys 4tx..4tx+3)
        float s[4][4] = {};
        #pragma unroll
        for (int kk = 0; kk < 64; kk++) {
            float a[4], b[4];
            #pragma unroll
            for (int i = 0; i < 4; i++) a[i] = Qs[(ty * 4 + i) * SW + kk];
            #pragma unroll
            for (int j = 0; j < 4; j++) b[j] = Ks[(tx * 4 + j) * SW + kk];
            #pragma unroll
            for (int i = 0; i < 4; i++)
                #pragma unroll
                for (int j = 0; j < 4; j++)
                    s[i][j] += a[i] * b[j];
        }

        // online softmax per row (row group = 16 lanes sharing ty: half-warp)
        #pragma unroll
        for (int i = 0; i < 4; i++) {
            #pragma unroll
            for (int j = 0; j < 4; j++) s[i][j] *= 0.125f;   // D^-0.5
            float mt = fmaxf(fmaxf(s[i][0], s[i][1]), fmaxf(s[i][2], s[i][3]));
            #pragma unroll
            for (int off = 8; off >= 1; off >>= 1)
                mt = fmaxf(mt, __shfl_xor_sync(0xffffffffu, mt, off));
            float nm = fmaxf(m_i[i], mt);
            float rs = 0.0f;
            #pragma unroll
            for (int j = 0; j < 4; j++) {
                s[i][j] = __expf(s[i][j] - nm);
                rs += s[i][j];
            }
            #pragma unroll
            for (int off = 8; off >= 1; off >>= 1)
                rs += __shfl_xor_sync(0xffffffffu, rs, off);
            float corr = __expf(m_i[i] - nm);                 // exp(-inf)=0 first iter
            l_i[i] = l_i[i] * corr + rs;
            m_i[i] = nm;
            #pragma unroll
            for (int j = 0; j < 4; j++) o[i][j] *= corr;
        }

        // stage P (prev-iter reads of Ps are fenced by the post-load sync above)
        #pragma unroll
        for (int i = 0; i < 4; i++)
            #pragma unroll
            for (int j = 0; j < 4; j++)
                Ps[(ty * 4 + i) * SW + tx * 4 + j] = s[i][j];
        __syncthreads();

        // O += P @ V  (this thread: rows 4ty..+3, D-cols 4tx..+3)
        #pragma unroll
        for (int kk = 0; kk < 64; kk++) {
            float a[4], b[4];
            #pragma unroll
            for (int i = 0; i < 4; i++) a[i] = Ps[(ty * 4 + i) * SW + kk];
            #pragma unroll
            for (int j = 0; j < 4; j++) b[j] = Vs[kk * SW + tx * 4 + j];
            #pragma unroll
            for (int i = 0; i < 4; i++)
                #pragma unroll
                for (int j = 0; j < 4; j++)
                    o[i][j] += a[i] * b[j];
        }
        __syncthreads();
    }

    // epilogue: normalize, write [B,N,H*D]
    const int bb = bh >> 4;
    const int h = bh & (Hh - 1);
    #pragma unroll
    for (int i = 0; i < 4; i++) {
        float inv = 1.0f / l_i[i];
        int row = q0 + ty * 4 + i;
        #pragma unroll
        for (int j = 0; j < 4; j++)
            g_ao[(bb * Nseq + row) * Emb + h * Dd + tx * 4 + j] = o[i][j] * inv;
    }
}

// ---------------------------------------------------------------------------
// Output projection: [4096,1024] @ [1024,1024] + bias -> d_out
// ---------------------------------------------------------------------------
__global__ __launch_bounds__(256) void proj_gemm_kernel(
    const float* __restrict__ Wp, const float* __restrict__ bias,
    float* __restrict__ out)
{
    __shared__ float As[16][65];
    __shared__ float Bs[16][65];

    const int tid = threadIdx.x;
    const int tx = tid & 15;
    const int ty = tid >> 4;
    const int m0 = blockIdx.y * 64;
    const int n0 = blockIdx.x * 64;

    float acc[4][4] = {};

    for (int k0 = 0; k0 < Emb; k0 += 16) {
        #pragma unroll
        for (int i = 0; i < 4; i++) {
            int e = tid + i * 256;
            As[e & 15][e >> 4] = g_ao[(m0 + (e >> 4)) * Emb + k0 + (e & 15)];
        }
        #pragma unroll
        for (int i = 0; i < 4; i++) {
            int e = tid + i * 256;
            Bs[e >> 6][e & 63] = Wp[(k0 + (e >> 6)) * Emb + n0 + (e & 63)];
        }
        __syncthreads();
        #pragma unroll
        for (int kk = 0; kk < 16; kk++) {
            float a[4], b[4];
            #pragma unroll
            for (int i = 0; i < 4; i++) a[i] = As[kk][ty * 4 + i];
            #pragma unroll
            for (int j = 0; j < 4; j++) b[j] = Bs[kk][tx * 4 + j];
            #pragma unroll
            for (int i = 0; i < 4; i++)
                #pragma unroll
                for (int j = 0; j < 4; j++)
                    acc[i][j] += a[i] * b[j];
        }
        __syncthreads();
    }

    #pragma unroll
    for (int i = 0; i < 4; i++) {
        int m = m0 + ty * 4 + i;
        #pragma unroll
        for (int j = 0; j < 4; j++) {
            int n = n0 + tx * 4 + j;
            out[m * Emb + n] = acc[i][j] + bias[n];
        }
    }
}

// ---------------------------------------------------------------------------
extern "C" void kernel_launch(void* const* d_in, const int* in_sizes, int n_in,
                              void* d_out, int out_size)
{
    const float* x      = (const float*)d_in[0];
    const float* w_qkv  = (const float*)d_in[1];
    const float* b_qkv  = (const float*)d_in[2];
    const float* w_proj = (const float*)d_in[3];
    const float* b_proj = (const float*)d_in[4];
    float* out = (float*)d_out;

    const int attn_smem = 4 * 64 * 65 * (int)sizeof(float);   // 66560 B
    cudaFuncSetAttribute(attn_kernel,
                         cudaFuncAttributeMaxDynamicSharedMemorySize, attn_smem);

    dim3 blk(256);
    qkv_gemm_kernel<<<dim3(E3 / 64, Mrows / 64), blk>>>(x, w_qkv, b_qkv);
    attn_kernel<<<dim3(Nseq / 64, Bsz * Hh), blk, attn_smem>>>();
    proj_gemm_kernel<<<dim3(Emb / 64, Mrows / 64), blk>>>(w_proj, b_proj, out);
}